// round 12
// baseline (speedup 1.0000x reference)
#include <cuda_runtime.h>

// NEAT feed-forward, fixed shapes:
//   N_MAX=10000, I=512, O=256, H=2000, BATCH=256, EDGE_P=0.02
// Raw active ids: inputs 0..511, outputs 512..767, hidden 768..2767 (all <2768).
// Compact positions: 0..511 inputs, 512..2511 hidden (tanh), 2512..2767 outputs.
//
// ROUND 12 = ROUND 11 + forward kernel launched 9x (idempotent) purely to
// attribute the ~900us between compute_levels (coef 1) and forward (coef 9).

#define NTOT   10000
#define NPOS   2768
#define NIN    512
#define NOUT   256
#define NOUTS  2512
#define NCOMP  (NPOS - NIN)   // 2256
#define CAP    160            // max preds stored (data max ~92)
#define NU     12             // register pairs per lane (covers nnz<=96)
#define NUS    96             // NU*8 sorted slots per node
#define G      4              // batch rows per CTA
#define NCTA   64             // 256/G
#define THREADS 1024
#define LMAX   2304

__device__ int   g_mode;                 // 0=uint8, 1=int32, 2=float32
__device__ int   g_cnt[NCOMP];           // atomic counters (zeroed each launch)
__device__ int2  g_pair[NCOMP * CAP];    // unordered append buffer
__device__ unsigned short g_lvl[NCOMP];
__device__ int   g_lvlOff[LMAX];
__device__ int   g_nLevels;
__device__ int   g_Lk[NCOMP];            // sorted slot: k | (cnt<<16)
__device__ int2  g_Lpair[NCOMP * NUS];   // rank-sorted pairs, slot-major

// ---------------------------------------------------------------------------
// Detect dtype of 'enabled' (first 4MB byte statistics) + zero g_cnt for the
// atomic-append build on every graph replay.
// ---------------------------------------------------------------------------
__global__ void detect_mode(const unsigned char* __restrict__ en)
{
    __shared__ int sGT1, sMod;
    if (threadIdx.x == 0) { sGT1 = 0; sMod = 0; }
    for (int i = threadIdx.x; i < NCOMP; i += blockDim.x) g_cnt[i] = 0;
    __syncthreads();
    int gt1 = 0, mod = 0;
    for (int i = threadIdx.x; i < (1 << 22); i += blockDim.x) {
        unsigned char v = en[i];
        gt1 += (v > 1);
        mod += (v == 1 && (i & 3) != 0);
    }
    atomicAdd(&sGT1, gt1);
    atomicAdd(&sMod, mod);
    __syncthreads();
    if (threadIdx.x == 0)
        g_mode = sGT1 ? 2 : (sMod ? 0 : 1);
}

// ---------------------------------------------------------------------------
// ROW-MAJOR edge build (coalesced). One warp per source row; lanes sweep
// target columns 512..2767; append to target lists via atomic slots.
// ---------------------------------------------------------------------------
__global__ void build_edges(const void* __restrict__ en_raw,
                            const float* __restrict__ w,
                            const int* __restrict__ topo)
{
    __shared__ unsigned short sPos[NPOS];   // raw id -> compact pos
    int tid = threadIdx.x;
    for (int p = tid; p < NPOS; p += blockDim.x)
        sPos[topo[p]] = (unsigned short)p;
    __syncthreads();

    int r    = (blockIdx.x * blockDim.x + tid) >> 5;   // source raw id
    int lane = tid & 31;
    if (r >= NPOS) return;

    const int mode = g_mode;
    const unsigned char* enu = (const unsigned char*)en_raw;
    const int*           eni = (const int*)en_raw;
    const float*         enf = (const float*)en_raw;

    int posr = sPos[r];
    long rowbase = (long)r * NTOT;

    for (int c = NIN + lane; c < NPOS; c += 32) {
        long off = rowbase + c;
        int ok;
        if      (mode == 0) ok = (enu[off] != 0);
        else if (mode == 1) ok = (eni[off] != 0);
        else                ok = (enf[off] != 0.f);
        if (ok) {
            int kc   = sPos[c] - NIN;
            int slot = atomicAdd(&g_cnt[kc], 1);
            if (slot < CAP)
                g_pair[kc * CAP + slot] =
                    make_int2(posr, __float_as_int(w[off]));
        }
    }
}

// ---------------------------------------------------------------------------
// Exact levels: fixpoint per 128-node window (8 lanes per node). UNCHANGED
// from round 11 (coef-1 term in the attribution equation).
// ---------------------------------------------------------------------------
__global__ void __launch_bounds__(THREADS, 1)
compute_levels()
{
    __shared__ unsigned short slvl[NPOS];
    int tid = threadIdx.x;
    for (int i = tid; i < NPOS; i += THREADS) slvl[i] = 0;
    __syncthreads();

    int sub = tid >> 3;
    int ln  = tid & 7;

    for (int base = NIN; base < NPOS; base += 128) {
        int k = base + sub;
        bool valid = (k < NPOS);
        int wg  = valid ? (k - NIN) : 0;
        int cnt = valid ? min(g_cnt[wg], CAP) : 0;

        int pos[NU];
        #pragma unroll
        for (int u = 0; u < NU; u++) {
            int t = ln + u * 8;
            pos[u] = (valid && t < cnt) ? __ldg(&g_pair[wg * CAP + t]).x : 0;
        }

        int prev = -1;
        for (;;) {
            int m = 0;
            #pragma unroll
            for (int u = 0; u < NU; u++) {
                int v = slvl[pos[u]];
                m = (v > m) ? v : m;
            }
            for (int t = NUS + ln; t < cnt; t += 8) {
                int v = slvl[__ldg(&g_pair[wg * CAP + t]).x];
                m = (v > m) ? v : m;
            }
            int v;
            v = __shfl_xor_sync(0xffffffffu, m, 4); m = (v > m) ? v : m;
            v = __shfl_xor_sync(0xffffffffu, m, 2); m = (v > m) ? v : m;
            v = __shfl_xor_sync(0xffffffffu, m, 1); m = (v > m) ? v : m;
            int nl = m + 1;
            int ch = 0;
            if (valid && ln == 0 && nl != prev) {
                slvl[k] = (unsigned short)nl;
                ch = 1;
            }
            prev = nl;
            if (!__syncthreads_or(ch)) break;
        }
    }

    for (int i = tid; i < NCOMP; i += THREADS)
        g_lvl[i] = slvl[NIN + i];
}

// ---------------------------------------------------------------------------
// Counting sort by level (unchanged).
// ---------------------------------------------------------------------------
__global__ void __launch_bounds__(THREADS, 1)
sort_levels()
{
    __shared__ int A[LMAX], Bm[LMAX], C[LMAX];
    __shared__ int sMax;
    int tid = threadIdx.x;
    if (tid == 0) sMax = 0;
    for (int i = tid; i < LMAX; i += THREADS) A[i] = 0;
    __syncthreads();

    int localMax = 0;
    for (int i = tid; i < NCOMP; i += THREADS) {
        int L = g_lvl[i];
        atomicAdd(&A[L], 1);
        localMax = (L > localMax) ? L : localMax;
    }
    atomicMax(&sMax, localMax);
    __syncthreads();

    int* src = A;
    int* dst = Bm;
    for (int d = 1; d < LMAX; d <<= 1) {
        for (int i = tid; i < LMAX; i += THREADS)
            dst[i] = src[i] + ((i >= d) ? src[i - d] : 0);
        __syncthreads();
        int* t = src; src = dst; dst = t;
    }
    for (int i = tid; i < LMAX; i += THREADS) {
        int ex = i ? src[i - 1] : 0;
        g_lvlOff[i] = ex;
        C[i] = ex;
    }
    if (tid == 0) g_nLevels = sMax;
    __syncthreads();

    for (int i = tid; i < NCOMP; i += THREADS) {
        int L = g_lvl[i];
        int slot = atomicAdd(&C[L], 1);
        int cnt = min(g_cnt[i], CAP);
        g_Lk[slot] = (NIN + i) | (cnt << 16);
    }
}

// ---------------------------------------------------------------------------
// Rank-sort each node's pairs into slot-major g_Lpair (unchanged).
// ---------------------------------------------------------------------------
__global__ void reorder_sorted()
{
    __shared__ int keys[8][NUS];
    int slot = (blockIdx.x * blockDim.x + threadIdx.x) >> 5;
    int lane = threadIdx.x & 31;
    int wloc = (threadIdx.x >> 5) & 7;
    if (slot >= NCOMP) return;

    int hdr = g_Lk[slot];
    int wg  = (hdr & 0xFFFF) - NIN;
    int cnt = hdr >> 16;
    if (cnt > NUS) cnt = NUS;
    const int2* src = g_pair + (long)wg * CAP;
    int2*       dst = g_Lpair + (long)slot * NUS;

    for (int t = lane; t < cnt; t += 32) keys[wloc][t] = src[t].x;
    for (int t = lane; t < NUS; t += 32) dst[t] = make_int2(0, 0);
    __syncwarp();

    for (int t = lane; t < cnt; t += 32) {
        int2 e = src[t];
        int rank = 0;
        for (int u = 0; u < cnt; u++) rank += (keys[wloc][u] < e.x);
        dst[rank] = e;
    }
}

// ---------------------------------------------------------------------------
// Level-synchronized forward (unchanged; launched 9x, idempotent — the
// coef-9 term in the attribution equation).
// ---------------------------------------------------------------------------
__global__ void __launch_bounds__(THREADS, 1)
neat_forward_lvl(const float* __restrict__ x,
                 float* __restrict__ out)
{
    __shared__ float sa[NPOS * G];   // 44.3 KB
    __shared__ int   sOff[520];

    int tid  = threadIdx.x;
    int lane = tid & 31;
    int warp = tid >> 5;
    int bg   = blockIdx.x;

    for (int t = tid; t < NIN * G; t += THREADS) {
        int i = t >> 2, bl = t & 3;
        sa[t] = x[(bg * G + bl) * NIN + i];
    }
    for (int i = tid; i < 520; i += THREADS)
        sOff[i] = g_lvlOff[i];
    __syncthreads();

    int nL = g_nLevels;
    int b  = lane & 3;
    int h  = lane >> 2;

    for (int L = 1; L <= nL; L++) {
        int s0 = (L < 519) ? sOff[L]     : __ldg(&g_lvlOff[L]);
        int s1 = (L < 518) ? sOff[L + 1] : __ldg(&g_lvlOff[L + 1]);

        for (int i = s0 + warp; i < s1; i += 32) {
            int hdr = __ldg(&g_Lk[i]);
            const int2* pp = g_Lpair + (long)i * NUS;

            int   pos[NU];
            float wv[NU];
            #pragma unroll
            for (int u = 0; u < NU; u++) {
                int2 e = __ldg(&pp[h + (u << 3)]);
                pos[u] = e.x;
                wv[u]  = __int_as_float(e.y);
            }

            float s = 0.f;
            #pragma unroll
            for (int u = 0; u < NU; u++)
                s += wv[u] * sa[pos[u] * G + b];

            s += __shfl_xor_sync(0xffffffffu, s, 16);
            s += __shfl_xor_sync(0xffffffffu, s, 8);
            s += __shfl_xor_sync(0xffffffffu, s, 4);

            int k = hdr & 0xFFFF;
            if (lane < 4)
                sa[k * G + lane] = (k >= NOUTS) ? s : tanhf(s);
        }
        __syncthreads();
    }

    for (int t = tid; t < NOUT * G; t += THREADS) {
        int o = t >> 2, bl = t & 3;
        out[(bg * G + bl) * NOUT + o] = sa[(NOUTS + o) * G + bl];
    }
}

extern "C" void kernel_launch(void* const* d_in, const int* in_sizes, int n_in,
                              void* d_out, int out_size)
{
    const float* x    = (const float*)d_in[0];
    const float* w    = (const float*)d_in[1];
    const void*  en   = d_in[2];
    const int*   topo = (const int*)d_in[5];
    float*       out  = (float*)d_out;

    int gridW = (NPOS * 32 + 255) / 256;
    int gridS = (NCOMP * 32 + 255) / 256;
    detect_mode<<<1, 256>>>((const unsigned char*)en);
    build_edges<<<gridW, 256>>>(en, w, topo);
    compute_levels<<<1, THREADS>>>();
    sort_levels<<<1, THREADS>>>();
    reorder_sorted<<<gridS, 256>>>();
    // Idempotent forward x9: dur = base + L + 9*F  =>  slope attributes F.
    for (int rep = 0; rep < 9; rep++)
        neat_forward_lvl<<<NCTA, THREADS>>>(x, out);
}

// round 13
// speedup vs baseline: 1.8961x; 1.8961x over previous
#include <cuda_runtime.h>

// NEAT feed-forward, fixed shapes:
//   N_MAX=10000, I=512, O=256, H=2000, BATCH=256, EDGE_P=0.02
// Raw active ids: inputs 0..511, outputs 512..767, hidden 768..2767 (all <2768).
// Compact positions: 0..511 inputs, 512..2511 hidden (tanh), 2512..2767 outputs.

#define NTOT   10000
#define NPOS   2768
#define NIN    512
#define NOUT   256
#define NOUTS  2512
#define NCOMP  (NPOS - NIN)   // 2256
#define CAP    160            // max preds stored (data max ~92)
#define NU     12             // register pairs per lane (covers nnz<=96)
#define NUS    96             // NU*8 sorted slots per node
#define G      4              // batch rows per CTA
#define NCTA   64             // 256/G
#define THREADS 1024
#define LMAX   2304
#define WIN    128            // level-window size

__device__ int   g_mode;                 // 0=uint8, 1=int32, 2=float32
__device__ int   g_cnt[NCOMP];           // atomic counters (zeroed each launch)
__device__ int2  g_pair[NCOMP * CAP];    // unordered append buffer
__device__ unsigned short g_lvl[NCOMP];
__device__ int   g_lvlOff[LMAX];
__device__ int   g_nLevels;
__device__ int   g_Lk[NCOMP];            // sorted slot: k | (cnt<<16)
__device__ int2  g_Lpair[NCOMP * NUS];   // rank-sorted pairs, slot-major

// ---------------------------------------------------------------------------
// Detect dtype of 'enabled' (first 4MB byte statistics) + zero g_cnt for the
// atomic-append build on every graph replay.
// ---------------------------------------------------------------------------
__global__ void detect_mode(const unsigned char* __restrict__ en)
{
    __shared__ int sGT1, sMod;
    if (threadIdx.x == 0) { sGT1 = 0; sMod = 0; }
    for (int i = threadIdx.x; i < NCOMP; i += blockDim.x) g_cnt[i] = 0;
    __syncthreads();
    int gt1 = 0, mod = 0;
    for (int i = threadIdx.x; i < (1 << 22); i += blockDim.x) {
        unsigned char v = en[i];
        gt1 += (v > 1);
        mod += (v == 1 && (i & 3) != 0);
    }
    atomicAdd(&sGT1, gt1);
    atomicAdd(&sMod, mod);
    __syncthreads();
    if (threadIdx.x == 0)
        g_mode = sGT1 ? 2 : (sMod ? 0 : 1);
}

// ---------------------------------------------------------------------------
// ROW-MAJOR edge build (coalesced). One warp per source row; lanes sweep
// target columns 512..2767; append to target lists via atomic slots.
// ---------------------------------------------------------------------------
__global__ void build_edges(const void* __restrict__ en_raw,
                            const float* __restrict__ w,
                            const int* __restrict__ topo)
{
    __shared__ unsigned short sPos[NPOS];   // raw id -> compact pos
    int tid = threadIdx.x;
    for (int p = tid; p < NPOS; p += blockDim.x)
        sPos[topo[p]] = (unsigned short)p;
    __syncthreads();

    int r    = (blockIdx.x * blockDim.x + tid) >> 5;   // source raw id
    int lane = tid & 31;
    if (r >= NPOS) return;

    const int mode = g_mode;
    const unsigned char* enu = (const unsigned char*)en_raw;
    const int*           eni = (const int*)en_raw;
    const float*         enf = (const float*)en_raw;

    int posr = sPos[r];
    long rowbase = (long)r * NTOT;

    for (int c = NIN + lane; c < NPOS; c += 32) {
        long off = rowbase + c;
        int ok;
        if      (mode == 0) ok = (enu[off] != 0);
        else if (mode == 1) ok = (eni[off] != 0);
        else                ok = (enf[off] != 0.f);
        if (ok) {
            int kc   = sPos[c] - NIN;
            int slot = atomicAdd(&g_cnt[kc], 1);
            if (slot < CAP)
                g_pair[kc * CAP + slot] =
                    make_int2(posr, __float_as_int(w[off]));
        }
    }
}

// ---------------------------------------------------------------------------
// Exact levels, invariant-hoisted. Per 128-node window:
//   Phase 1 (once): m0 = max(level[preds with pos < base])  — those are FINAL.
//   Phase 2 fixpoint: only the (rare, ~0.6/lane) in-window preds are re-read.
// Level values are identical to a global fixpoint; ~15x fewer LDS per iter.
// ---------------------------------------------------------------------------
__global__ void __launch_bounds__(THREADS, 1)
compute_levels()
{
    __shared__ unsigned short slvl[NPOS];
    int tid = threadIdx.x;
    for (int i = tid; i < NPOS; i += THREADS) slvl[i] = 0;
    __syncthreads();

    int sub = tid >> 3;   // node-in-window 0..127
    int ln  = tid & 7;    // 8 lanes per node

    for (int base = NIN; base < NPOS; base += WIN) {
        int k = base + sub;
        bool valid = (k < NPOS);
        int wg  = valid ? (k - NIN) : 0;
        int cnt = valid ? min(g_cnt[wg], CAP) : 0;

        // Phase 1: hoist the out-of-window max; stash in-window preds.
        int m0 = 0;
        int inw[4];
        int nin = 0;
        bool ovf = false;
        int allpos[NU];
        #pragma unroll
        for (int u = 0; u < NU; u++) {
            int t = ln + u * 8;
            int p = (valid && t < cnt) ? __ldg(&g_pair[wg * CAP + t]).x : 0;
            allpos[u] = p;
            if (p < base) {
                int v = slvl[p];
                m0 = (v > m0) ? v : m0;
            } else if (nin < 4) {
                inw[nin++] = p;
            } else {
                ovf = true;
            }
        }
        for (int t = NUS + ln; t < cnt; t += 8) {      // tail (rare)
            int p = __ldg(&g_pair[wg * CAP + t]).x;
            if (p < base) {
                int v = slvl[p];
                m0 = (v > m0) ? v : m0;
            } else {
                ovf = true;
            }
        }
        #pragma unroll
        for (int u = 0; u < 4; u++)
            if (u >= nin) inw[u] = 0;   // slvl[0]=0: stable sentinel

        // Phase 2: cheap fixpoint over in-window preds only.
        int prev = -1;
        for (;;) {
            int m = m0;
            if (!ovf) {
                #pragma unroll
                for (int u = 0; u < 4; u++) {
                    int v = slvl[inw[u]];
                    m = (v > m) ? v : m;
                }
            } else {   // statistically unreachable full rescan (correctness net)
                #pragma unroll
                for (int u = 0; u < NU; u++) {
                    int v = slvl[allpos[u]];
                    m = (v > m) ? v : m;
                }
                for (int t = NUS + ln; t < cnt; t += 8) {
                    int v = slvl[__ldg(&g_pair[wg * CAP + t]).x];
                    m = (v > m) ? v : m;
                }
            }
            int v;
            v = __shfl_xor_sync(0xffffffffu, m, 4); m = (v > m) ? v : m;
            v = __shfl_xor_sync(0xffffffffu, m, 2); m = (v > m) ? v : m;
            v = __shfl_xor_sync(0xffffffffu, m, 1); m = (v > m) ? v : m;
            int nl = m + 1;
            int ch = 0;
            if (valid && ln == 0 && nl != prev) {
                slvl[k] = (unsigned short)nl;
                ch = 1;
            }
            prev = nl;
            if (!__syncthreads_or(ch)) break;
        }
    }

    for (int i = tid; i < NCOMP; i += THREADS)
        g_lvl[i] = slvl[NIN + i];
}

// ---------------------------------------------------------------------------
// Counting sort by level (unchanged).
// ---------------------------------------------------------------------------
__global__ void __launch_bounds__(THREADS, 1)
sort_levels()
{
    __shared__ int A[LMAX], Bm[LMAX], C[LMAX];
    __shared__ int sMax;
    int tid = threadIdx.x;
    if (tid == 0) sMax = 0;
    for (int i = tid; i < LMAX; i += THREADS) A[i] = 0;
    __syncthreads();

    int localMax = 0;
    for (int i = tid; i < NCOMP; i += THREADS) {
        int L = g_lvl[i];
        atomicAdd(&A[L], 1);
        localMax = (L > localMax) ? L : localMax;
    }
    atomicMax(&sMax, localMax);
    __syncthreads();

    int* src = A;
    int* dst = Bm;
    for (int d = 1; d < LMAX; d <<= 1) {
        for (int i = tid; i < LMAX; i += THREADS)
            dst[i] = src[i] + ((i >= d) ? src[i - d] : 0);
        __syncthreads();
        int* t = src; src = dst; dst = t;
    }
    for (int i = tid; i < LMAX; i += THREADS) {
        int ex = i ? src[i - 1] : 0;
        g_lvlOff[i] = ex;
        C[i] = ex;
    }
    if (tid == 0) g_nLevels = sMax;
    __syncthreads();

    for (int i = tid; i < NCOMP; i += THREADS) {
        int L = g_lvl[i];
        int slot = atomicAdd(&C[L], 1);
        int cnt = min(g_cnt[i], CAP);
        g_Lk[slot] = (NIN + i) | (cnt << 16);
    }
}

// ---------------------------------------------------------------------------
// Rank-sort each node's pairs into slot-major g_Lpair (unchanged).
// ---------------------------------------------------------------------------
__global__ void reorder_sorted()
{
    __shared__ int keys[8][NUS];
    int slot = (blockIdx.x * blockDim.x + threadIdx.x) >> 5;
    int lane = threadIdx.x & 31;
    int wloc = (threadIdx.x >> 5) & 7;
    if (slot >= NCOMP) return;

    int hdr = g_Lk[slot];
    int wg  = (hdr & 0xFFFF) - NIN;
    int cnt = hdr >> 16;
    if (cnt > NUS) cnt = NUS;
    const int2* src = g_pair + (long)wg * CAP;
    int2*       dst = g_Lpair + (long)slot * NUS;

    for (int t = lane; t < cnt; t += 32) keys[wloc][t] = src[t].x;
    for (int t = lane; t < NUS; t += 32) dst[t] = make_int2(0, 0);
    __syncwarp();

    for (int t = lane; t < cnt; t += 32) {
        int2 e = src[t];
        int rank = 0;
        for (int u = 0; u < cnt; u++) rank += (keys[wloc][u] < e.x);
        dst[rank] = e;
    }
}

// ---------------------------------------------------------------------------
// Level-synchronized forward (unchanged; F measured at ~99us via R12 slope).
// ---------------------------------------------------------------------------
__global__ void __launch_bounds__(THREADS, 1)
neat_forward_lvl(const float* __restrict__ x,
                 float* __restrict__ out)
{
    __shared__ float sa[NPOS * G];   // 44.3 KB
    __shared__ int   sOff[520];

    int tid  = threadIdx.x;
    int lane = tid & 31;
    int warp = tid >> 5;
    int bg   = blockIdx.x;

    for (int t = tid; t < NIN * G; t += THREADS) {
        int i = t >> 2, bl = t & 3;
        sa[t] = x[(bg * G + bl) * NIN + i];
    }
    for (int i = tid; i < 520; i += THREADS)
        sOff[i] = g_lvlOff[i];
    __syncthreads();

    int nL = g_nLevels;
    int b  = lane & 3;
    int h  = lane >> 2;

    for (int L = 1; L <= nL; L++) {
        int s0 = (L < 519) ? sOff[L]     : __ldg(&g_lvlOff[L]);
        int s1 = (L < 518) ? sOff[L + 1] : __ldg(&g_lvlOff[L + 1]);

        for (int i = s0 + warp; i < s1; i += 32) {
            int hdr = __ldg(&g_Lk[i]);
            const int2* pp = g_Lpair + (long)i * NUS;

            int   pos[NU];
            float wv[NU];
            #pragma unroll
            for (int u = 0; u < NU; u++) {
                int2 e = __ldg(&pp[h + (u << 3)]);
                pos[u] = e.x;
                wv[u]  = __int_as_float(e.y);
            }

            float s = 0.f;
            #pragma unroll
            for (int u = 0; u < NU; u++)
                s += wv[u] * sa[pos[u] * G + b];

            s += __shfl_xor_sync(0xffffffffu, s, 16);
            s += __shfl_xor_sync(0xffffffffu, s, 8);
            s += __shfl_xor_sync(0xffffffffu, s, 4);

            int k = hdr & 0xFFFF;
            if (lane < 4)
                sa[k * G + lane] = (k >= NOUTS) ? s : tanhf(s);
        }
        __syncthreads();
    }

    for (int t = tid; t < NOUT * G; t += THREADS) {
        int o = t >> 2, bl = t & 3;
        out[(bg * G + bl) * NOUT + o] = sa[(NOUTS + o) * G + bl];
    }
}

extern "C" void kernel_launch(void* const* d_in, const int* in_sizes, int n_in,
                              void* d_out, int out_size)
{
    const float* x    = (const float*)d_in[0];
    const float* w    = (const float*)d_in[1];
    const void*  en   = d_in[2];
    const int*   topo = (const int*)d_in[5];
    float*       out  = (float*)d_out;

    int gridW = (NPOS * 32 + 255) / 256;
    int gridS = (NCOMP * 32 + 255) / 256;
    detect_mode<<<1, 256>>>((const unsigned char*)en);
    build_edges<<<gridW, 256>>>(en, w, topo);
    compute_levels<<<1, THREADS>>>();
    sort_levels<<<1, THREADS>>>();
    reorder_sorted<<<gridS, 256>>>();
    neat_forward_lvl<<<NCTA, THREADS>>>(x, out);
}